// round 2
// baseline (speedup 1.0000x reference)
#include <cuda_runtime.h>
#include <cuda_bf16.h>
#include <cstdint>

#define NNODES 65536
#define NEDGES 262144

// ============================ device scratch ============================
__device__ __align__(256) __nv_bfloat16 g_xb   [NNODES * 256];
__device__ __align__(256) __nv_bfloat16 g_hnode[NNODES * 128];
__device__ __align__(256) __nv_bfloat16 g_grow [NNODES * 256];
__device__ __align__(256) __nv_bfloat16 g_gcol [NNODES * 256];
__device__ __align__(256) __nv_bfloat16 g_eab  [NEDGES * 64];
__device__ __align__(256) __nv_bfloat16 g_h0   [(size_t)NEDGES * 256];
__device__ __align__(256) __nv_bfloat16 g_h1   [(size_t)NEDGES * 256];
// weight images, [NOUT][K] bf16 row-major (k contiguous) == B col-major for mma row.col
__device__ __align__(256) __nv_bfloat16 g_Bx [128 * 256];
__device__ __align__(256) __nv_bfloat16 g_B0a[256 * 128];
__device__ __align__(256) __nv_bfloat16 g_B0b[256 * 128];
__device__ __align__(256) __nv_bfloat16 g_B0c[256 * 64];
__device__ __align__(256) __nv_bfloat16 g_Bm [8][256 * 256];
__device__ int g_idx64;

// ============================ PTX helpers (base PTX only!) ============================
__device__ __forceinline__ uint32_t smem_u32(const void* p) {
    uint32_t a;
    asm("{ .reg .u64 t; cvta.to.shared.u64 t, %1; cvt.u32.u64 %0, t; }" : "=r"(a) : "l"(p));
    return a;
}
__device__ __forceinline__ void cp16(uint32_t dst, const void* src) {
    asm volatile("cp.async.cg.shared.global [%0], [%1], 16;" :: "r"(dst), "l"(src));
}
__device__ __forceinline__ void cp_commit() {
    asm volatile("cp.async.commit_group;" ::: "memory");
}
template <int N>
__device__ __forceinline__ void cp_wait() {
    asm volatile("cp.async.wait_group %0;" :: "n"(N) : "memory");
}
__device__ __forceinline__ void ldm_x4(uint32_t* r, uint32_t addr) {
    asm volatile("ldmatrix.sync.aligned.m8n8.x4.shared.b16 {%0,%1,%2,%3}, [%4];"
                 : "=r"(r[0]), "=r"(r[1]), "=r"(r[2]), "=r"(r[3]) : "r"(addr));
}
__device__ __forceinline__ void ldm_x2(uint32_t* r, uint32_t addr) {
    asm volatile("ldmatrix.sync.aligned.m8n8.x2.shared.b16 {%0,%1}, [%2];"
                 : "=r"(r[0]), "=r"(r[1]) : "r"(addr));
}
__device__ __forceinline__ void mma_bf16(float* c, const uint32_t* a, const uint32_t* b) {
    asm volatile(
        "mma.sync.aligned.m16n8k16.row.col.f32.bf16.bf16.f32 "
        "{%0,%1,%2,%3}, {%4,%5,%6,%7}, {%8,%9}, {%0,%1,%2,%3};"
        : "+f"(c[0]), "+f"(c[1]), "+f"(c[2]), "+f"(c[3])
        : "r"(a[0]), "r"(a[1]), "r"(a[2]), "r"(a[3]), "r"(b[0]), "r"(b[1]));
}

// ============================ prep kernels ============================
__global__ void detect_idx64(const unsigned* __restrict__ ei) {
    if (threadIdx.x == 0 && blockIdx.x == 0) {
        int is64 = 1;
        for (int i = 0; i < 512; i++)
            if (ei[2 * i + 1] != 0u) { is64 = 0; break; }
        g_idx64 = is64;
    }
}

__global__ void conv_f32_bf16(const float* __restrict__ src, __nv_bfloat16* __restrict__ dst, int n) {
    for (int i = blockIdx.x * blockDim.x + threadIdx.x; i < n; i += gridDim.x * blockDim.x)
        dst[i] = __float2bfloat16(src[i]);
}

// edge_attr [E,16] fp32 -> [E,64] bf16 zero-padded
__global__ void prep_eab(const float* __restrict__ ea, __nv_bfloat16* __restrict__ out) {
    int n = NEDGES * 64;
    for (int i = blockIdx.x * blockDim.x + threadIdx.x; i < n; i += gridDim.x * blockDim.x) {
        int e = i >> 6, k = i & 63;
        out[i] = __float2bfloat16(k < 16 ? ea[e * 16 + k] : 0.f);
    }
}

// W fp32 [row0+k][n] (leading dim ldW) -> Bimg[n][k] bf16, zero-pad k >= Ksrc
__global__ void prep_B(const float* __restrict__ W, int row0, int ldW, int Ksrc,
                       int Kpad, int NOUT, __nv_bfloat16* __restrict__ Bimg) {
    int total = NOUT * Kpad;
    for (int i = blockIdx.x * blockDim.x + threadIdx.x; i < total; i += gridDim.x * blockDim.x) {
        int n = i / Kpad, k = i % Kpad;
        float v = (k < Ksrc) ? W[(size_t)(row0 + k) * ldW + n] : 0.f;
        Bimg[i] = __float2bfloat16(v);
    }
}

// ============================ HMMA GEMM ============================
// Out[M, NOUT] = A[M, K] @ B^T  (B stored [NOUT][K]), optional bias + leaky, bf16 out.
// CTA tile 128(M) x 128(N), 8 warps in 2x4 grid (warp tile 64x32), Kc = 64, 2-stage cp.async.
template <int K, int NOUT, bool LEAKY, bool HASBIAS>
__global__ void __launch_bounds__(256)
gemm_mma(const __nv_bfloat16* __restrict__ A, const __nv_bfloat16* __restrict__ B,
         const float* __restrict__ bias, __nv_bfloat16* __restrict__ Out) {
    static_assert(K % 64 == 0, "");
    constexpr int KT = K / 64;
    extern __shared__ char smem[];
    const uint32_t sb = smem_u32(smem);
    // per-stage layout: A tile 128x64 bf16 (16KB) then B tile 128x64 (16KB); 2 stages
    constexpr uint32_t STAGE = 32768, BOFF = 16384;

    const int tid = threadIdx.x;
    const int lane = tid & 31, warp = tid >> 5;
    const int warp_m = warp & 1;        // 0..1 -> m offset *64
    const int warp_n = warp >> 1;       // 0..3 -> n offset *32
    const size_t m0 = (size_t)blockIdx.x * 128;
    const int n0 = blockIdx.y * 128;

    float acc[4][4][4];
    #pragma unroll
    for (int i = 0; i < 4; i++)
        #pragma unroll
        for (int j = 0; j < 4; j++)
            #pragma unroll
            for (int q = 0; q < 4; q++) acc[i][j][q] = 0.f;

    // ---- global -> smem stage loader (Kc = 64 cols = 8 uint4 per row) ----
    auto load_stage = [&](int stage, int kt) {
        const uint32_t base = sb + stage * STAGE;
        #pragma unroll
        for (int i = 0; i < 4; i++) {                     // A: 1024 uint4 / 256 thr
            int idx = tid + i * 256;
            int r = idx >> 3, c8 = idx & 7;
            uint32_t dst = base + r * 128 + (((c8 ^ (r & 7))) << 4);
            cp16(dst, A + (m0 + r) * K + kt * 64 + c8 * 8);
        }
        #pragma unroll
        for (int i = 0; i < 4; i++) {                     // B
            int idx = tid + i * 256;
            int r = idx >> 3, c8 = idx & 7;
            uint32_t dst = base + BOFF + r * 128 + (((c8 ^ (r & 7))) << 4);
            cp16(dst, B + (size_t)(n0 + r) * K + kt * 64 + c8 * 8);
        }
    };

    load_stage(0, 0);
    cp_commit();

    for (int kt = 0; kt < KT; kt++) {
        if (kt + 1 < KT) { load_stage((kt + 1) & 1, kt + 1); cp_commit(); cp_wait<1>(); }
        else             { cp_wait<0>(); }
        __syncthreads();

        const uint32_t abase = sb + (kt & 1) * STAGE;
        const uint32_t bbase = abase + BOFF;
        #pragma unroll
        for (int ks = 0; ks < 4; ks++) {
            uint32_t af[4][4];
            #pragma unroll
            for (int mi = 0; mi < 4; mi++) {
                int r = warp_m * 64 + mi * 16 + (lane & 15);
                int c8 = ks * 2 + (lane >> 4);
                ldm_x4(af[mi], abase + r * 128 + ((c8 ^ (r & 7)) << 4));
            }
            uint32_t bf2[4][2];
            #pragma unroll
            for (int ni = 0; ni < 4; ni++) {
                int r = warp_n * 32 + ni * 8 + (lane & 7);
                int c8 = ks * 2 + ((lane >> 3) & 1);
                ldm_x2(bf2[ni], bbase + r * 128 + ((c8 ^ (r & 7)) << 4));
            }
            #pragma unroll
            for (int mi = 0; mi < 4; mi++)
                #pragma unroll
                for (int ni = 0; ni < 4; ni++)
                    mma_bf16(acc[mi][ni], af[mi], bf2[ni]);
        }
        __syncthreads();
    }

    // ---- epilogue: bias + leaky + bf16 pack ----
    const int g = lane >> 2;
    #pragma unroll
    for (int ni = 0; ni < 4; ni++) {
        const int col = n0 + warp_n * 32 + ni * 8 + ((lane & 3) << 1);
        float bb0 = 0.f, bb1 = 0.f;
        if (HASBIAS) { bb0 = __ldg(bias + col); bb1 = __ldg(bias + col + 1); }
        #pragma unroll
        for (int mi = 0; mi < 4; mi++) {
            const size_t r0 = m0 + warp_m * 64 + mi * 16 + g;
            float v0 = acc[mi][ni][0] + bb0, v1 = acc[mi][ni][1] + bb1;
            float v2 = acc[mi][ni][2] + bb0, v3 = acc[mi][ni][3] + bb1;
            if (LEAKY) {
                v0 = v0 >= 0.f ? v0 : 0.01f * v0;  v1 = v1 >= 0.f ? v1 : 0.01f * v1;
                v2 = v2 >= 0.f ? v2 : 0.01f * v2;  v3 = v3 >= 0.f ? v3 : 0.01f * v3;
            }
            __nv_bfloat162 p0 = __floats2bfloat162_rn(v0, v1);
            __nv_bfloat162 p1 = __floats2bfloat162_rn(v2, v3);
            *(uint32_t*)(Out + r0 * NOUT + col)       = *(uint32_t*)&p0;
            *(uint32_t*)(Out + (r0 + 8) * NOUT + col) = *(uint32_t*)&p1;
        }
    }
}

// ============================ gather + combine ============================
// h0[e] = leaky(h0[e] (= ea@W0c + b0) + g_row[row[e]] + g_col[col[e]])
__global__ void gather_combine(const int* __restrict__ ei,
                               const __nv_bfloat16* __restrict__ gr,
                               const __nv_bfloat16* __restrict__ gc,
                               __nv_bfloat16* __restrict__ h0) {
    __shared__ int srow[64], scol[64];
    const int t = threadIdx.x;
    const long e0 = (long)blockIdx.x * 64;
    const int is64 = g_idx64;
    if (t < 64) {
        long e = e0 + t;
        if (is64) { srow[t] = ei[2 * e]; scol[t] = ei[2 * (NEDGES + e)]; }
        else      { srow[t] = ei[e];     scol[t] = ei[NEDGES + e]; }
    }
    __syncthreads();
    const int cp = t & 127;   // bf16x2 column pair 0..127
    const int eo = t >> 7;    // which of 2 edges this half-block handles
    for (int i = eo; i < 64; i += 2) {
        long e = e0 + i;
        const __nv_bfloat162* grp = (const __nv_bfloat162*)(gr + (size_t)srow[i] * 256);
        const __nv_bfloat162* gcp = (const __nv_bfloat162*)(gc + (size_t)scol[i] * 256);
        __nv_bfloat162* hp = (__nv_bfloat162*)(h0 + (size_t)e * 256);
        float2 a = __bfloat1622float2(hp[cp]);
        float2 b = __bfloat1622float2(grp[cp]);
        float2 c = __bfloat1622float2(gcp[cp]);
        float v0 = a.x + b.x + c.x, v1 = a.y + b.y + c.y;
        v0 = v0 >= 0.f ? v0 : 0.01f * v0;
        v1 = v1 >= 0.f ? v1 : 0.01f * v1;
        hp[cp] = __floats2bfloat162_rn(v0, v1);
    }
}

// ============================ head: logits + log_softmax ============================
__global__ void final_head(const __nv_bfloat16* __restrict__ h,
                           const float* __restrict__ Wl, const float* __restrict__ bl,
                           float* __restrict__ out) {
    const int gw = (blockIdx.x * blockDim.x + threadIdx.x) >> 5;   // global warp, 4096 total
    const int lid = threadIdx.x & 31;
    float w[8][3];
    #pragma unroll
    for (int j = 0; j < 8; j++) {
        int c = lid * 8 + j;
        #pragma unroll
        for (int k = 0; k < 3; k++) w[j][k] = Wl[c * 3 + k];
    }
    const float b0 = bl[0], b1 = bl[1], b2 = bl[2];
    const int EPW = NEDGES / 4096;  // 64
    for (int e = gw * EPW; e < (gw + 1) * EPW; e++) {
        uint4 raw = *(const uint4*)(h + (size_t)e * 256 + lid * 8);
        const __nv_bfloat16* hb = (const __nv_bfloat16*)&raw;
        float a0 = 0.f, a1 = 0.f, a2 = 0.f;
        #pragma unroll
        for (int j = 0; j < 8; j++) {
            float xv = __bfloat162float(hb[j]);
            a0 += xv * w[j][0]; a1 += xv * w[j][1]; a2 += xv * w[j][2];
        }
        #pragma unroll
        for (int o = 16; o; o >>= 1) {
            a0 += __shfl_xor_sync(0xFFFFFFFFu, a0, o);
            a1 += __shfl_xor_sync(0xFFFFFFFFu, a1, o);
            a2 += __shfl_xor_sync(0xFFFFFFFFu, a2, o);
        }
        if (lid == 0) {
            float l0 = a0 + b0, l1 = a1 + b1, l2 = a2 + b2;
            float m = fmaxf(l0, fmaxf(l1, l2));
            float ls = m + logf(expf(l0 - m) + expf(l1 - m) + expf(l2 - m));
            out[e * 3 + 0] = l0 - ls;
            out[e * 3 + 1] = l1 - ls;
            out[e * 3 + 2] = l2 - ls;
        }
    }
}

// ============================ host ============================
extern "C" void kernel_launch(void* const* d_in, const int* in_sizes, int n_in,
                              void* d_out, int out_size) {
    const float* x  = (const float*)d_in[0];
    const int*   ei = (const int*)d_in[1];
    const float* ea = (const float*)d_in[2];
    const float* Wx = (const float*)d_in[3];
    const float* bx = (const float*)d_in[4];
    const float* W0 = (const float*)d_in[5];
    const float* b0 = (const float*)d_in[6];
    const float* Wm = (const float*)d_in[7];
    const float* bm = (const float*)d_in[8];
    const float* Wl = (const float*)d_in[9];
    const float* bl = (const float*)d_in[10];
    float* out = (float*)d_out;

    void* p;
    cudaGetSymbolAddress(&p, g_xb);    __nv_bfloat16* xb    = (__nv_bfloat16*)p;
    cudaGetSymbolAddress(&p, g_hnode); __nv_bfloat16* hnode = (__nv_bfloat16*)p;
    cudaGetSymbolAddress(&p, g_grow);  __nv_bfloat16* grow  = (__nv_bfloat16*)p;
    cudaGetSymbolAddress(&p, g_gcol);  __nv_bfloat16* gcol  = (__nv_bfloat16*)p;
    cudaGetSymbolAddress(&p, g_eab);   __nv_bfloat16* eab   = (__nv_bfloat16*)p;
    cudaGetSymbolAddress(&p, g_h0);    __nv_bfloat16* h0    = (__nv_bfloat16*)p;
    cudaGetSymbolAddress(&p, g_h1);    __nv_bfloat16* h1    = (__nv_bfloat16*)p;
    cudaGetSymbolAddress(&p, g_Bx);    __nv_bfloat16* Bx    = (__nv_bfloat16*)p;
    cudaGetSymbolAddress(&p, g_B0a);   __nv_bfloat16* B0a   = (__nv_bfloat16*)p;
    cudaGetSymbolAddress(&p, g_B0b);   __nv_bfloat16* B0b   = (__nv_bfloat16*)p;
    cudaGetSymbolAddress(&p, g_B0c);   __nv_bfloat16* B0c   = (__nv_bfloat16*)p;
    cudaGetSymbolAddress(&p, g_Bm);    __nv_bfloat16* Bm    = (__nv_bfloat16*)p;

    constexpr int SMEM = 65536;
    cudaFuncSetAttribute(gemm_mma<256, 128, true,  true >, cudaFuncAttributeMaxDynamicSharedMemorySize, SMEM);
    cudaFuncSetAttribute(gemm_mma<128, 256, false, false>, cudaFuncAttributeMaxDynamicSharedMemorySize, SMEM);
    cudaFuncSetAttribute(gemm_mma<64,  256, false, true >, cudaFuncAttributeMaxDynamicSharedMemorySize, SMEM);
    cudaFuncSetAttribute(gemm_mma<256, 256, true,  true >, cudaFuncAttributeMaxDynamicSharedMemorySize, SMEM);

    // --- prep ---
    detect_idx64<<<1, 32>>>((const unsigned*)ei);
    conv_f32_bf16<<<4096, 256>>>(x, xb, NNODES * 256);
    prep_eab<<<4096, 256>>>(ea, eab);
    prep_B<<<64, 256>>>(Wx, 0,   128, 256, 256, 128, Bx);
    prep_B<<<64, 256>>>(W0, 0,   256, 128, 128, 256, B0a);
    prep_B<<<64, 256>>>(W0, 128, 256, 128, 128, 256, B0b);
    prep_B<<<64, 256>>>(W0, 256, 256, 16,  64,  256, B0c);
    for (int i = 0; i < 8; i++)
        prep_B<<<64, 256>>>(Wm + (size_t)i * 65536, 0, 256, 256, 256, 256, Bm + (size_t)i * 65536);

    // --- node MLP: h_node = leaky(x @ Wx + bx) ---
    gemm_mma<256, 128, true, true><<<dim3(NNODES / 128, 1), 256, SMEM>>>(xb, Bx, bx, hnode);
    // --- node-level edge-GEMM precompute: g_row/g_col = h_node @ W0[0:128]/W0[128:256] ---
    gemm_mma<128, 256, false, false><<<dim3(NNODES / 128, 2), 256, SMEM>>>(hnode, B0a, nullptr, grow);
    gemm_mma<128, 256, false, false><<<dim3(NNODES / 128, 2), 256, SMEM>>>(hnode, B0b, nullptr, gcol);
    // --- edge-attr part (+b0) into h0 ---
    gemm_mma<64, 256, false, true><<<dim3(NEDGES / 128, 2), 256, SMEM>>>(eab, B0c, b0, h0);
    // --- gather + combine + leaky ---
    gather_combine<<<NEDGES / 64, 256>>>(ei, grow, gcol, h0);
    // --- 8 hidden layers ---
    __nv_bfloat16* cur = h0;
    __nv_bfloat16* nxt = h1;
    for (int i = 0; i < 8; i++) {
        gemm_mma<256, 256, true, true><<<dim3(NEDGES / 128, 2), 256, SMEM>>>(
            cur, Bm + (size_t)i * 65536, bm + (size_t)i * 256, nxt);
        __nv_bfloat16* t = cur; cur = nxt; nxt = t;
    }
    // --- head ---
    final_head<<<512, 256>>>(cur, Wl, bl, out);
}

// round 3
// speedup vs baseline: 1.5804x; 1.5804x over previous
#include <cuda_runtime.h>
#include <cuda_bf16.h>
#include <cstdint>

#define NNODES 65536
#define NEDGES 262144

// ============================ device scratch ============================
__device__ __align__(256) __nv_bfloat16 g_xb   [NNODES * 256];
__device__ __align__(256) __nv_bfloat16 g_hnode[NNODES * 128];
__device__ __align__(256) __nv_bfloat16 g_grow [NNODES * 256];
__device__ __align__(256) __nv_bfloat16 g_gcol [NNODES * 256];
__device__ __align__(256) __nv_bfloat16 g_eab  [NEDGES * 64];
__device__ __align__(256) __nv_bfloat16 g_h0   [(size_t)NEDGES * 256];
// weight images, [NOUT][K] bf16 row-major (k contiguous) == B col-major for mma row.col
__device__ __align__(256) __nv_bfloat16 g_Bx [128 * 256];
__device__ __align__(256) __nv_bfloat16 g_B0a[256 * 128];
__device__ __align__(256) __nv_bfloat16 g_B0b[256 * 128];
__device__ __align__(256) __nv_bfloat16 g_B0c[256 * 64];
__device__ __align__(256) __nv_bfloat16 g_Bm [8][256 * 256];
__device__ int g_idx64;

// ============================ PTX helpers (base PTX only) ============================
__device__ __forceinline__ uint32_t smem_u32(const void* p) {
    uint32_t a;
    asm("{ .reg .u64 t; cvta.to.shared.u64 t, %1; cvt.u32.u64 %0, t; }" : "=r"(a) : "l"(p));
    return a;
}
__device__ __forceinline__ void cp16(uint32_t dst, const void* src) {
    asm volatile("cp.async.cg.shared.global [%0], [%1], 16;" :: "r"(dst), "l"(src));
}
__device__ __forceinline__ void cp_commit() {
    asm volatile("cp.async.commit_group;" ::: "memory");
}
template <int N>
__device__ __forceinline__ void cp_wait() {
    asm volatile("cp.async.wait_group %0;" :: "n"(N) : "memory");
}
__device__ __forceinline__ void ldm_x4(uint32_t* r, uint32_t addr) {
    asm volatile("ldmatrix.sync.aligned.m8n8.x4.shared.b16 {%0,%1,%2,%3}, [%4];"
                 : "=r"(r[0]), "=r"(r[1]), "=r"(r[2]), "=r"(r[3]) : "r"(addr));
}
__device__ __forceinline__ void ldm_x2(uint32_t* r, uint32_t addr) {
    asm volatile("ldmatrix.sync.aligned.m8n8.x2.shared.b16 {%0,%1}, [%2];"
                 : "=r"(r[0]), "=r"(r[1]) : "r"(addr));
}
__device__ __forceinline__ void mma_bf16(float* c, const uint32_t* a, const uint32_t* b) {
    asm volatile(
        "mma.sync.aligned.m16n8k16.row.col.f32.bf16.bf16.f32 "
        "{%0,%1,%2,%3}, {%4,%5,%6,%7}, {%8,%9}, {%0,%1,%2,%3};"
        : "+f"(c[0]), "+f"(c[1]), "+f"(c[2]), "+f"(c[3])
        : "r"(a[0]), "r"(a[1]), "r"(a[2]), "r"(a[3]), "r"(b[0]), "r"(b[1]));
}

// ============================ prep kernels ============================
__global__ void detect_idx64(const unsigned* __restrict__ ei) {
    if (threadIdx.x == 0 && blockIdx.x == 0) {
        int is64 = 1;
        for (int i = 0; i < 512; i++)
            if (ei[2 * i + 1] != 0u) { is64 = 0; break; }
        g_idx64 = is64;
    }
}

__global__ void conv_f32_bf16(const float* __restrict__ src, __nv_bfloat16* __restrict__ dst, int n) {
    for (int i = blockIdx.x * blockDim.x + threadIdx.x; i < n; i += gridDim.x * blockDim.x)
        dst[i] = __float2bfloat16(src[i]);
}

// edge_attr [E,16] fp32 -> [E,64] bf16 zero-padded
__global__ void prep_eab(const float* __restrict__ ea, __nv_bfloat16* __restrict__ out) {
    int n = NEDGES * 64;
    for (int i = blockIdx.x * blockDim.x + threadIdx.x; i < n; i += gridDim.x * blockDim.x) {
        int e = i >> 6, k = i & 63;
        out[i] = __float2bfloat16(k < 16 ? ea[e * 16 + k] : 0.f);
    }
}

// W fp32 [row0+k][n] (leading dim ldW) -> Bimg[n][k] bf16, zero-pad k >= Ksrc
__global__ void prep_B(const float* __restrict__ W, int row0, int ldW, int Ksrc,
                       int Kpad, int NOUT, __nv_bfloat16* __restrict__ Bimg) {
    int total = NOUT * Kpad;
    for (int i = blockIdx.x * blockDim.x + threadIdx.x; i < total; i += gridDim.x * blockDim.x) {
        int n = i / Kpad, k = i % Kpad;
        float v = (k < Ksrc) ? W[(size_t)(row0 + k) * ldW + n] : 0.f;
        Bimg[i] = __float2bfloat16(v);
    }
}

// ============================ generic HMMA GEMM (prep stages) ============================
template <int K, int NOUT, bool LEAKY, bool HASBIAS>
__global__ void __launch_bounds__(256)
gemm_mma(const __nv_bfloat16* __restrict__ A, const __nv_bfloat16* __restrict__ B,
         const float* __restrict__ bias, __nv_bfloat16* __restrict__ Out) {
    static_assert(K % 64 == 0, "");
    constexpr int KT = K / 64;
    extern __shared__ char smem[];
    const uint32_t sb = smem_u32(smem);
    constexpr uint32_t STAGE = 32768, BOFF = 16384;

    const int tid = threadIdx.x;
    const int lane = tid & 31, warp = tid >> 5;
    const int warp_m = warp & 1;
    const int warp_n = warp >> 1;
    const size_t m0 = (size_t)blockIdx.x * 128;
    const int n0 = blockIdx.y * 128;

    float acc[4][4][4];
    #pragma unroll
    for (int i = 0; i < 4; i++)
        #pragma unroll
        for (int j = 0; j < 4; j++)
            #pragma unroll
            for (int q = 0; q < 4; q++) acc[i][j][q] = 0.f;

    auto load_stage = [&](int stage, int kt) {
        const uint32_t base = sb + stage * STAGE;
        #pragma unroll
        for (int i = 0; i < 4; i++) {
            int idx = tid + i * 256;
            int r = idx >> 3, c8 = idx & 7;
            uint32_t dst = base + r * 128 + (((c8 ^ (r & 7))) << 4);
            cp16(dst, A + (m0 + r) * K + kt * 64 + c8 * 8);
        }
        #pragma unroll
        for (int i = 0; i < 4; i++) {
            int idx = tid + i * 256;
            int r = idx >> 3, c8 = idx & 7;
            uint32_t dst = base + BOFF + r * 128 + (((c8 ^ (r & 7))) << 4);
            cp16(dst, B + (size_t)(n0 + r) * K + kt * 64 + c8 * 8);
        }
    };

    load_stage(0, 0);
    cp_commit();

    for (int kt = 0; kt < KT; kt++) {
        if (kt + 1 < KT) { load_stage((kt + 1) & 1, kt + 1); cp_commit(); cp_wait<1>(); }
        else             { cp_wait<0>(); }
        __syncthreads();

        const uint32_t abase = sb + (kt & 1) * STAGE;
        const uint32_t bbase = abase + BOFF;
        #pragma unroll
        for (int ks = 0; ks < 4; ks++) {
            uint32_t af[4][4];
            #pragma unroll
            for (int mi = 0; mi < 4; mi++) {
                int r = warp_m * 64 + mi * 16 + (lane & 15);
                int c8 = ks * 2 + (lane >> 4);
                ldm_x4(af[mi], abase + r * 128 + ((c8 ^ (r & 7)) << 4));
            }
            uint32_t bf2[4][2];
            #pragma unroll
            for (int ni = 0; ni < 4; ni++) {
                int r = warp_n * 32 + ni * 8 + (lane & 7);
                int c8 = ks * 2 + ((lane >> 3) & 1);
                ldm_x2(bf2[ni], bbase + r * 128 + ((c8 ^ (r & 7)) << 4));
            }
            #pragma unroll
            for (int mi = 0; mi < 4; mi++)
                #pragma unroll
                for (int ni = 0; ni < 4; ni++)
                    mma_bf16(acc[mi][ni], af[mi], bf2[ni]);
        }
        __syncthreads();
    }

    const int g = lane >> 2;
    #pragma unroll
    for (int ni = 0; ni < 4; ni++) {
        const int col = n0 + warp_n * 32 + ni * 8 + ((lane & 3) << 1);
        float bb0 = 0.f, bb1 = 0.f;
        if (HASBIAS) { bb0 = __ldg(bias + col); bb1 = __ldg(bias + col + 1); }
        #pragma unroll
        for (int mi = 0; mi < 4; mi++) {
            const size_t r0 = m0 + warp_m * 64 + mi * 16 + g;
            float v0 = acc[mi][ni][0] + bb0, v1 = acc[mi][ni][1] + bb1;
            float v2 = acc[mi][ni][2] + bb0, v3 = acc[mi][ni][3] + bb1;
            if (LEAKY) {
                v0 = v0 >= 0.f ? v0 : 0.01f * v0;  v1 = v1 >= 0.f ? v1 : 0.01f * v1;
                v2 = v2 >= 0.f ? v2 : 0.01f * v2;  v3 = v3 >= 0.f ? v3 : 0.01f * v3;
            }
            __nv_bfloat162 p0 = __floats2bfloat162_rn(v0, v1);
            __nv_bfloat162 p1 = __floats2bfloat162_rn(v2, v3);
            *(uint32_t*)(Out + r0 * NOUT + col)       = *(uint32_t*)&p0;
            *(uint32_t*)(Out + (r0 + 8) * NOUT + col) = *(uint32_t*)&p1;
        }
    }
}

// ============================ gather + combine ============================
__global__ void gather_combine(const int* __restrict__ ei,
                               const __nv_bfloat16* __restrict__ gr,
                               const __nv_bfloat16* __restrict__ gc,
                               __nv_bfloat16* __restrict__ h0) {
    __shared__ int srow[64], scol[64];
    const int t = threadIdx.x;
    const long e0 = (long)blockIdx.x * 64;
    const int is64 = g_idx64;
    if (t < 64) {
        long e = e0 + t;
        if (is64) { srow[t] = ei[2 * e]; scol[t] = ei[2 * (NEDGES + e)]; }
        else      { srow[t] = ei[e];     scol[t] = ei[NEDGES + e]; }
    }
    __syncthreads();
    const int cp = t & 127;
    const int eo = t >> 7;
    for (int i = eo; i < 64; i += 2) {
        long e = e0 + i;
        const __nv_bfloat162* grp = (const __nv_bfloat162*)(gr + (size_t)srow[i] * 256);
        const __nv_bfloat162* gcp = (const __nv_bfloat162*)(gc + (size_t)scol[i] * 256);
        __nv_bfloat162* hp = (__nv_bfloat162*)(h0 + (size_t)e * 256);
        float2 a = __bfloat1622float2(hp[cp]);
        float2 b = __bfloat1622float2(grp[cp]);
        float2 c = __bfloat1622float2(gcp[cp]);
        float v0 = a.x + b.x + c.x, v1 = a.y + b.y + c.y;
        v0 = v0 >= 0.f ? v0 : 0.01f * v0;
        v1 = v1 >= 0.f ? v1 : 0.01f * v1;
        hp[cp] = __floats2bfloat162_rn(v0, v1);
    }
}

// ============================ fused 8 mid layers + head ============================
// Each CTA: 128 edges. 8 warps, warp tile = 16(M) x 256(N), activations chained in
// registers (C-fragment of layer l == A-fragment of layer l+1). Weights stream
// L2 -> SMEM via 4-slot x 32KB cp.async ring. Head (256->3) + log_softmax fused.
__global__ void __launch_bounds__(256, 1)
fused_mid(const __nv_bfloat16* __restrict__ h0, const __nv_bfloat16* __restrict__ Bm,
          const float* __restrict__ bm, const float* __restrict__ Wl,
          const float* __restrict__ bl, float* __restrict__ out) {
    extern __shared__ char smem[];
    const uint32_t sb = smem_u32(smem);
    constexpr uint32_t RINGOFF = 65536;               // A tile: [0, 64KB)
    constexpr uint32_t BIASOFF = 65536 + 131072;      // ring: 4 x 32KB
    float* sbias = (float*)(smem + BIASOFF);          // 8*256 fp32
    float* sWl   = (float*)(smem + BIASOFF + 8192);   // 256*3 fp32
    float* sbl   = (float*)(smem + BIASOFF + 8192 + 3072);

    const int tid = threadIdx.x, lane = tid & 31, warp = tid >> 5;
    const size_t m0 = (size_t)blockIdx.x * 128;

    // small params -> smem
    for (int i = tid; i < 2048; i += 256) sbias[i] = bm[i];
    for (int i = tid; i < 768; i += 256) sWl[i] = Wl[i];
    if (tid < 3) sbl[tid] = bl[tid];

    // B ring loader: step s -> layer s>>2, k-half s&3, slot s&3
    auto loadB = [&](int s) {
        const uint32_t base = sb + RINGOFF + (uint32_t)(s & 3) * 32768u;
        const __nv_bfloat16* src = Bm + (size_t)(s >> 2) * 65536 + (s & 3) * 64;
        #pragma unroll
        for (int i = 0; i < 8; i++) {
            int idx = tid + i * 256;
            int r = idx >> 3, c8 = idx & 7;
            cp16(base + r * 128 + ((c8 ^ (r & 7)) << 4), src + (size_t)r * 256 + c8 * 8);
        }
    };

    // A tile (h0, 128x256) -> smem as 4 chunks of [128][64]
    #pragma unroll
    for (int kc = 0; kc < 4; kc++)
        #pragma unroll
        for (int i = 0; i < 4; i++) {
            int idx = tid + i * 256;
            int r = idx >> 3, c8 = idx & 7;
            cp16(sb + kc * 16384 + r * 128 + ((c8 ^ (r & 7)) << 4),
                 h0 + (m0 + r) * 256 + kc * 64 + c8 * 8);
        }
    cp_commit();
    loadB(0); cp_commit();
    loadB(1); cp_commit();

    cp_wait<2>();         // A tile done (B0/B1 may be in flight)
    __syncthreads();

    // ldmatrix A -> packed activation fragments pa[32][2]
    // pa[t][0] = (row g, cols 8t+2j..+1), pa[t][1] = (row g+8, same cols)
    uint32_t pa[32][2];
    #pragma unroll
    for (int s = 0; s < 16; s++) {
        int rr = warp * 16 + (lane & 15);
        int cc = (s & 3) * 2 + (lane >> 4);
        uint32_t f[4];
        ldm_x4(f, sb + (s >> 2) * 16384 + rr * 128 + ((cc ^ (rr & 7)) << 4));
        pa[2 * s][0] = f[0]; pa[2 * s][1] = f[1];
        pa[2 * s + 1][0] = f[2]; pa[2 * s + 1][1] = f[3];
    }

    const int j = lane & 3;
    for (int l = 0; l < 8; ++l) {
        float acc[32][4];
        // bias folded into accumulator init
        const float2* b2 = (const float2*)(sbias + (l << 8));
        #pragma unroll
        for (int ni = 0; ni < 32; ni++) {
            float2 bb = b2[4 * ni + j];
            acc[ni][0] = bb.x; acc[ni][1] = bb.y; acc[ni][2] = bb.x; acc[ni][3] = bb.y;
        }
        #pragma unroll
        for (int kh = 0; kh < 4; kh++) {
            const int s = l * 4 + kh;
            cp_wait<1>();            // slot s ready (only newest group pending)
            __syncthreads();
            if (s + 2 < 32) loadB(s + 2);
            cp_commit();
            const uint32_t bbase = sb + RINGOFF + (uint32_t)(s & 3) * 32768u;
            const int rr_lo = ((lane >> 4) << 3) + (lane & 7);
            #pragma unroll
            for (int ksl = 0; ksl < 4; ksl++) {
                const int ai = kh * 8 + ksl * 2;
                uint32_t a[4] = {pa[ai][0], pa[ai][1], pa[ai + 1][0], pa[ai + 1][1]};
                const int cc = ksl * 2 + ((lane >> 3) & 1);
                #pragma unroll
                for (int np = 0; np < 16; np++) {
                    int rr = np * 16 + rr_lo;
                    uint32_t bf[4];
                    ldm_x4(bf, bbase + rr * 128 + ((cc ^ (rr & 7)) << 4));
                    mma_bf16(acc[2 * np], a, bf);
                    mma_bf16(acc[2 * np + 1], a, bf + 2);
                }
            }
        }
        // leaky + pack back into activation fragments
        #pragma unroll
        for (int ni = 0; ni < 32; ni++) {
            float v0 = acc[ni][0], v1 = acc[ni][1], v2 = acc[ni][2], v3 = acc[ni][3];
            v0 = v0 >= 0.f ? v0 : 0.01f * v0;  v1 = v1 >= 0.f ? v1 : 0.01f * v1;
            v2 = v2 >= 0.f ? v2 : 0.01f * v2;  v3 = v3 >= 0.f ? v3 : 0.01f * v3;
            __nv_bfloat162 p0 = __floats2bfloat162_rn(v0, v1);
            __nv_bfloat162 p1 = __floats2bfloat162_rn(v2, v3);
            pa[ni][0] = *(uint32_t*)&p0;
            pa[ni][1] = *(uint32_t*)&p1;
        }
    }

    // ---- fused head: logits = h @ Wlast + blast, then log_softmax ----
    float a3[2][3] = {{0.f, 0.f, 0.f}, {0.f, 0.f, 0.f}};
    #pragma unroll
    for (int t = 0; t < 32; t++) {
        float2 x = __bfloat1622float2(*(__nv_bfloat162*)&pa[t][0]);  // row g
        float2 y = __bfloat1622float2(*(__nv_bfloat162*)&pa[t][1]);  // row g+8
        const int c0 = 8 * t + 2 * j;
        float w00 = sWl[c0 * 3 + 0], w01 = sWl[c0 * 3 + 1], w02 = sWl[c0 * 3 + 2];
        float w10 = sWl[c0 * 3 + 3], w11 = sWl[c0 * 3 + 4], w12 = sWl[c0 * 3 + 5];
        a3[0][0] += x.x * w00 + x.y * w10;
        a3[0][1] += x.x * w01 + x.y * w11;
        a3[0][2] += x.x * w02 + x.y * w12;
        a3[1][0] += y.x * w00 + y.y * w10;
        a3[1][1] += y.x * w01 + y.y * w11;
        a3[1][2] += y.x * w02 + y.y * w12;
    }
    #pragma unroll
    for (int off = 1; off <= 2; off <<= 1) {
        #pragma unroll
        for (int r = 0; r < 2; r++)
            #pragma unroll
            for (int c = 0; c < 3; c++)
                a3[r][c] += __shfl_xor_sync(0xFFFFFFFFu, a3[r][c], off);
    }
    if (j == 0) {
        const int g = lane >> 2;
        const float bb0 = sbl[0], bb1 = sbl[1], bb2 = sbl[2];
        #pragma unroll
        for (int r = 0; r < 2; r++) {
            size_t e = m0 + warp * 16 + g + 8 * r;
            float l0 = a3[r][0] + bb0, l1 = a3[r][1] + bb1, l2 = a3[r][2] + bb2;
            float m = fmaxf(l0, fmaxf(l1, l2));
            float ls = m + logf(expf(l0 - m) + expf(l1 - m) + expf(l2 - m));
            out[e * 3 + 0] = l0 - ls;
            out[e * 3 + 1] = l1 - ls;
            out[e * 3 + 2] = l2 - ls;
        }
    }
}

// ============================ host ============================
extern "C" void kernel_launch(void* const* d_in, const int* in_sizes, int n_in,
                              void* d_out, int out_size) {
    const float* x  = (const float*)d_in[0];
    const int*   ei = (const int*)d_in[1];
    const float* ea = (const float*)d_in[2];
    const float* Wx = (const float*)d_in[3];
    const float* bx = (const float*)d_in[4];
    const float* W0 = (const float*)d_in[5];
    const float* b0 = (const float*)d_in[6];
    const float* Wm = (const float*)d_in[7];
    const float* bm = (const float*)d_in[8];
    const float* Wl = (const float*)d_in[9];
    const float* bl = (const float*)d_in[10];
    float* out = (float*)d_out;

    void* p;
    cudaGetSymbolAddress(&p, g_xb);    __nv_bfloat16* xb    = (__nv_bfloat16*)p;
    cudaGetSymbolAddress(&p, g_hnode); __nv_bfloat16* hnode = (__nv_bfloat16*)p;
    cudaGetSymbolAddress(&p, g_grow);  __nv_bfloat16* grow  = (__nv_bfloat16*)p;
    cudaGetSymbolAddress(&p, g_gcol);  __nv_bfloat16* gcol  = (__nv_bfloat16*)p;
    cudaGetSymbolAddress(&p, g_eab);   __nv_bfloat16* eab   = (__nv_bfloat16*)p;
    cudaGetSymbolAddress(&p, g_h0);    __nv_bfloat16* h0    = (__nv_bfloat16*)p;
    cudaGetSymbolAddress(&p, g_Bx);    __nv_bfloat16* Bx    = (__nv_bfloat16*)p;
    cudaGetSymbolAddress(&p, g_B0a);   __nv_bfloat16* B0a   = (__nv_bfloat16*)p;
    cudaGetSymbolAddress(&p, g_B0b);   __nv_bfloat16* B0b   = (__nv_bfloat16*)p;
    cudaGetSymbolAddress(&p, g_B0c);   __nv_bfloat16* B0c   = (__nv_bfloat16*)p;
    cudaGetSymbolAddress(&p, g_Bm);    __nv_bfloat16* Bm    = (__nv_bfloat16*)p;

    constexpr int SMEM = 65536;
    constexpr int FSMEM = 65536 + 131072 + 8192 + 3072 + 16;   // 207,904
    cudaFuncSetAttribute(gemm_mma<256, 128, true,  true >, cudaFuncAttributeMaxDynamicSharedMemorySize, SMEM);
    cudaFuncSetAttribute(gemm_mma<128, 256, false, false>, cudaFuncAttributeMaxDynamicSharedMemorySize, SMEM);
    cudaFuncSetAttribute(gemm_mma<64,  256, false, true >, cudaFuncAttributeMaxDynamicSharedMemorySize, SMEM);
    cudaFuncSetAttribute(fused_mid, cudaFuncAttributeMaxDynamicSharedMemorySize, FSMEM);

    // --- prep ---
    detect_idx64<<<1, 32>>>((const unsigned*)ei);
    conv_f32_bf16<<<4096, 256>>>(x, xb, NNODES * 256);
    prep_eab<<<4096, 256>>>(ea, eab);
    prep_B<<<64, 256>>>(Wx, 0,   128, 256, 256, 128, Bx);
    prep_B<<<64, 256>>>(W0, 0,   256, 128, 128, 256, B0a);
    prep_B<<<64, 256>>>(W0, 128, 256, 128, 128, 256, B0b);
    prep_B<<<64, 256>>>(W0, 256, 256, 16,  64,  256, B0c);
    for (int i = 0; i < 8; i++)
        prep_B<<<64, 256>>>(Wm + (size_t)i * 65536, 0, 256, 256, 256, 256, Bm + (size_t)i * 65536);

    // --- node MLP: h_node = leaky(x @ Wx + bx) ---
    gemm_mma<256, 128, true, true><<<dim3(NNODES / 128, 1), 256, SMEM>>>(xb, Bx, bx, hnode);
    // --- node-level edge-GEMM precompute ---
    gemm_mma<128, 256, false, false><<<dim3(NNODES / 128, 2), 256, SMEM>>>(hnode, B0a, nullptr, grow);
    gemm_mma<128, 256, false, false><<<dim3(NNODES / 128, 2), 256, SMEM>>>(hnode, B0b, nullptr, gcol);
    // --- edge-attr part (+b0) into h0 ---
    gemm_mma<64, 256, false, true><<<dim3(NEDGES / 128, 2), 256, SMEM>>>(eab, B0c, b0, h0);
    // --- gather + combine + leaky ---
    gather_combine<<<NEDGES / 64, 256>>>(ei, grow, gcol, h0);
    // --- fused: 8 hidden layers + head + log_softmax ---
    fused_mid<<<NEDGES / 128, 256, FSMEM>>>(h0, Bm, bm, Wl, bl, out);
}